// round 4
// baseline (speedup 1.0000x reference)
#include <cuda_runtime.h>
#include <cstdint>
#include <cstddef>

#define B_ 16
#define LK_ 8192
#define D_ 1024
#define H_ 1024
#define M_TOTAL (B_*LK_)

#define TM 128          // CTA rows (b*LK flattened)
#define TN 128          // h-chunk width
#define TK 16           // K-stage depth
#define SA_K 20         // padded A stride (conflict-free: (20g+t)%32 distinct)
#define SB_N 136        // padded B stride (conflict-free: (136t+g)%32 = (8t+g) distinct)
#define NCH (H_/TN)     // 8
#define KST (D_/TK)     // 64

// scratch for q-projection [B, H]
__device__ float g_qp[B_*H_];

// ---------------- kernel 1: qp[b,h] = sum_d queries[b,0,d] * W_q[d,h] ----------------
__global__ __launch_bounds__(256) void qproj_kernel(const float* __restrict__ q,
                                                    const float* __restrict__ Wq) {
    int b = blockIdx.y;
    int h = blockIdx.x * 256 + threadIdx.x;
    const float* qr = q + b * D_;
    float acc = 0.f;
#pragma unroll 8
    for (int d = 0; d < D_; ++d) acc = fmaf(qr[d], Wq[d * H_ + h], acc);
    g_qp[b * H_ + h] = acc;
}

// ---------------- helpers ----------------
__device__ __forceinline__ uint32_t f2tf32(float f) {
    uint32_t r; asm("cvt.rna.tf32.f32 %0, %1;" : "=r"(r) : "f"(f)); return r;
}
__device__ __forceinline__ void cp16(void* dst, const void* src) {
    uint32_t d = (uint32_t)__cvta_generic_to_shared(dst);
    asm volatile("cp.async.cg.shared.global [%0], [%1], 16;\n" :: "r"(d), "l"(src));
}
__device__ __forceinline__ float tanh_fast(float x) {
    // accurate-enough tanh: 2 MUFU (EX2 + RCP), abs err ~1e-6; clamp avoids inf/inf
    float xc = fminf(fmaxf(x, -15.f), 15.f);
    float e = __expf(2.f * xc);
    return __fdividef(e - 1.f, e + 1.f);
}

__device__ __forceinline__ void load_stage(float (*sAb)[SA_K], float (*sBb)[SB_N],
                                           const float* __restrict__ keys,
                                           const float* __restrict__ Wk,
                                           int m_base, int nc, int ks, int tid) {
    int k0 = ks * TK;
    // A: 128 rows x 16 floats (64B/row) = 512 x 16B chunks
#pragma unroll
    for (int i = 0; i < 2; ++i) {
        int c = tid + i * 256;
        int row = c >> 2, kq = c & 3;
        cp16(&sAb[row][kq * 4], keys + (size_t)(m_base + row) * D_ + k0 + kq * 4);
    }
    // B: 16 rows x 128 floats (512B/row contiguous) = 512 x 16B chunks
#pragma unroll
    for (int i = 0; i < 2; ++i) {
        int c = tid + i * 256;
        int r = c >> 5, nq = c & 31;
        cp16(&sBb[r][nq * 4], Wk + (size_t)(k0 + r) * H_ + nc * TN + nq * 4);
    }
}

// ---------------- kernel 2: fused keys@W_k -> tanh -> dot(w_v) ----------------
__global__ __launch_bounds__(256) void attn_kernel(const float* __restrict__ keys,
                                                   const float* __restrict__ Wk,
                                                   const float* __restrict__ wv,
                                                   float* __restrict__ out) {
    __shared__ __align__(16) float sA[2][TM][SA_K];   // 20.0 KB
    __shared__ __align__(16) float sB[2][TK][SB_N];   // 17.0 KB
    __shared__ float s_qp[TN], s_wv[TN], s_score[TM];
    __shared__ float s_red[TM][4];                    // deterministic reduction slots

    const int tid  = threadIdx.x;
    const int lane = tid & 31, warp = tid >> 5;
    const int wm = warp >> 2, wn = warp & 3;          // 2 x 4 warp grid, warp tile 64x32
    const int g = lane >> 2, t = lane & 3;
    const int m_base = blockIdx.x * TM;
    const int b = m_base >> 13;                        // 8192 rows per batch, tiles aligned

    if (tid < TM) s_score[tid] = 0.f;

    for (int nc = 0; nc < NCH; ++nc) {
        __syncthreads();   // prior epilogue done before s_qp/s_wv overwrite
        if (tid < TN) {
            s_qp[tid] = g_qp[b * H_ + nc * TN + tid];
            s_wv[tid] = wv[nc * TN + tid];
        }

        float acc[4][4][4];
#pragma unroll
        for (int mi = 0; mi < 4; ++mi)
#pragma unroll
            for (int ni = 0; ni < 4; ++ni)
#pragma unroll
                for (int r = 0; r < 4; ++r) acc[mi][ni][r] = 0.f;

        // prologue
        load_stage(sA[0], sB[0], keys, Wk, m_base, nc, 0, tid);
        asm volatile("cp.async.commit_group;\n");

        for (int ks = 0; ks < KST; ++ks) {
            int buf = ks & 1;
            if (ks + 1 < KST) {
                load_stage(sA[buf ^ 1], sB[buf ^ 1], keys, Wk, m_base, nc, ks + 1, tid);
                asm volatile("cp.async.commit_group;\n");
                asm volatile("cp.async.wait_group 1;\n");
            } else {
                asm volatile("cp.async.wait_group 0;\n");
            }
            __syncthreads();

#pragma unroll
            for (int k8 = 0; k8 < 2; ++k8) {
                uint32_t a[4][4], bb[4][2];
#pragma unroll
                for (int mi = 0; mi < 4; ++mi) {
                    int mr = wm * 64 + mi * 16 + g;
                    a[mi][0] = f2tf32(sA[buf][mr    ][k8 * 8 + t    ]);
                    a[mi][1] = f2tf32(sA[buf][mr + 8][k8 * 8 + t    ]);
                    a[mi][2] = f2tf32(sA[buf][mr    ][k8 * 8 + t + 4]);
                    a[mi][3] = f2tf32(sA[buf][mr + 8][k8 * 8 + t + 4]);
                }
#pragma unroll
                for (int ni = 0; ni < 4; ++ni) {
                    int ncol = wn * 32 + ni * 8 + g;
                    bb[ni][0] = f2tf32(sB[buf][k8 * 8 + t    ][ncol]);
                    bb[ni][1] = f2tf32(sB[buf][k8 * 8 + t + 4][ncol]);
                }
#pragma unroll
                for (int mi = 0; mi < 4; ++mi)
#pragma unroll
                    for (int ni = 0; ni < 4; ++ni)
                        asm volatile(
                            "mma.sync.aligned.m16n8k8.row.col.f32.tf32.tf32.f32 "
                            "{%0,%1,%2,%3},{%4,%5,%6,%7},{%8,%9},{%0,%1,%2,%3};"
                            : "+f"(acc[mi][ni][0]), "+f"(acc[mi][ni][1]),
                              "+f"(acc[mi][ni][2]), "+f"(acc[mi][ni][3])
                            : "r"(a[mi][0]), "r"(a[mi][1]), "r"(a[mi][2]), "r"(a[mi][3]),
                              "r"(bb[ni][0]), "r"(bb[ni][1]));
            }
            __syncthreads();   // protect buf before it is refilled two stages later
        }

        // epilogue: tanh(qp + acc) * wv, reduce 8 cols via shuffle, park in s_red
#pragma unroll
        for (int mi = 0; mi < 4; ++mi) {
            float p0 = 0.f, p1 = 0.f;
#pragma unroll
            for (int ni = 0; ni < 4; ++ni) {
                int c0 = wn * 32 + ni * 8 + 2 * t;
                float q0 = s_qp[c0], q1 = s_qp[c0 + 1];
                float w0 = s_wv[c0], w1 = s_wv[c0 + 1];
                p0 += tanh_fast(q0 + acc[mi][ni][0]) * w0 + tanh_fast(q1 + acc[mi][ni][1]) * w1;
                p1 += tanh_fast(q0 + acc[mi][ni][2]) * w0 + tanh_fast(q1 + acc[mi][ni][3]) * w1;
            }
            p0 += __shfl_xor_sync(0xffffffffu, p0, 1);
            p0 += __shfl_xor_sync(0xffffffffu, p0, 2);
            p1 += __shfl_xor_sync(0xffffffffu, p1, 1);
            p1 += __shfl_xor_sync(0xffffffffu, p1, 2);
            if (t == 0) {
                int r0 = wm * 64 + mi * 16 + g;
                s_red[r0    ][wn] = p0;
                s_red[r0 + 8][wn] = p1;
            }
        }
        __syncthreads();
        if (tid < TM)
            s_score[tid] += s_red[tid][0] + s_red[tid][1] + s_red[tid][2] + s_red[tid][3];
    }

    __syncthreads();
    if (tid < TM) out[m_base + tid] = s_score[tid];
}

// ---------------- launch ----------------
extern "C" void kernel_launch(void* const* d_in, const int* in_sizes, int n_in,
                              void* d_out, int out_size) {
    (void)in_sizes; (void)n_in; (void)out_size;
    const float* queries = (const float*)d_in[0];   // [16,1,1024]
    const float* keys    = (const float*)d_in[1];   // [16,8192,1024]
    const float* Wq      = (const float*)d_in[2];   // [1024,1024]
    const float* Wk      = (const float*)d_in[3];   // [1024,1024]
    const float* wv      = (const float*)d_in[4];   // [1024,1]
    float* out = (float*)d_out;                     // [16,8192]

    qproj_kernel<<<dim3(H_ / 256, B_), 256>>>(queries, Wq);
    attn_kernel<<<M_TOTAL / TM, 256>>>(keys, Wk, wv, out);
}